// round 8
// baseline (speedup 1.0000x reference)
#include <cuda_runtime.h>
#include <cuda_bf16.h>
#include <cstdint>

// tcgen05 exists only in the compute_103a pass; plain sm_103 compiles empty stubs.
#if defined(__CUDA_ARCH__) && defined(__CUDA_ARCH_FEAT_SM103_ALL)
#define HAS_TC 1
#else
#define HAS_TC 0
#endif

constexpr int Bb = 32, Np = 512, Dd = 512;

// ---------------- scratch (__device__ globals; alloc-free rule) -------------
__device__ __align__(16) __nv_bfloat16 g_xhi [(size_t)Bb * Np * Dd];
__device__ __align__(16) __nv_bfloat16 g_xlo [(size_t)Bb * Np * Dd];
__device__ __align__(16) __nv_bfloat16 g_wthi[(size_t)Dd * Dd];
__device__ __align__(16) __nv_bfloat16 g_wtlo[(size_t)Dd * Dd];
__device__ __align__(16) __nv_bfloat16 g_xwhi[(size_t)Bb * Np * Dd];
__device__ __align__(16) __nv_bfloat16 g_xwlo[(size_t)Bb * Np * Dd];

// ---------------- common helpers -------------------------------------------
__device__ __forceinline__ uint32_t smem_u32(const void* p) {
    uint32_t a;
    asm("{ .reg .u64 t; cvta.to.shared.u64 t, %1; cvt.u32.u64 %0, t; }"
        : "=r"(a) : "l"(p));
    return a;
}
__device__ __forceinline__ void cp_async16(uint32_t dst, const void* src) {
    asm volatile("cp.async.cg.shared.global [%0], [%1], 16;"
                 :: "r"(dst), "l"(src));
}
#define CP_COMMIT()  asm volatile("cp.async.commit_group;" ::: "memory")
#define CP_WAIT(n)   asm volatile("cp.async.wait_group %0;" :: "n"(n) : "memory")

// ---------------- conversion kernels ---------------------------------------
__global__ __launch_bounds__(256) void conv_x_kernel(const float4* __restrict__ X) {
    size_t i = (size_t)blockIdx.x * 256 + threadIdx.x;
    float4 v = X[i];
    union { __nv_bfloat16 b[4]; uint2 u; } H, L;
    const float* f = &v.x;
    #pragma unroll
    for (int j = 0; j < 4; j++) {
        __nv_bfloat16 h = __float2bfloat16_rn(f[j]);
        H.b[j] = h;
        L.b[j] = __float2bfloat16_rn(f[j] - __bfloat162float(h));
    }
    reinterpret_cast<uint2*>(g_xhi)[i] = H.u;
    reinterpret_cast<uint2*>(g_xlo)[i] = L.u;
}

__global__ __launch_bounds__(256) void conv_w_kernel(const float* __restrict__ W) {
    __shared__ float t[32][33];
    int tx = threadIdx.x, ty = threadIdx.y;          // 32 x 8
    int bx = blockIdx.x * 32, by = blockIdx.y * 32;  // bx: n-block, by: k-block
    #pragma unroll
    for (int r = 0; r < 4; r++)
        t[ty + r * 8][tx] = W[(size_t)(by + ty + r * 8) * Dd + bx + tx];
    __syncthreads();
    #pragma unroll
    for (int r = 0; r < 4; r++) {
        int n = bx + ty + r * 8, kk = by + tx;
        float v = t[tx][ty + r * 8];                  // = W[kk][n]
        __nv_bfloat16 h = __float2bfloat16_rn(v);
        g_wthi[(size_t)n * Dd + kk] = h;
        g_wtlo[(size_t)n * Dd + kk] = __float2bfloat16_rn(v - __bfloat162float(h));
    }
}

// ===========================================================================
// tcgen05 bf16x3 GEMM, 128(M) x 512(N) per CTA (single wave, 128 CTAs).
// K pipelined in 32 iters of K=16; 4 independent SW32 buffers, load-ahead 3.
// Each iter: 2 N-halves (N=256 MMA) x 3 split terms = 6 MMAs.
// ===========================================================================
constexpr int TBM = 128;
constexpr int NITER = 32;                            // 512 / 16
constexpr int A_T = TBM * 32;                        // 4096 B (128 rows x 32B)
constexpr int B_T = Np * 32;                         // 16384 B (512 rows x 32B)
constexpr int BUF_BYTES = 2 * A_T + 2 * B_T;         // 40960
constexpr int T_OFF_MBAR  = 8;                       // 4 mbarriers
constexpr int T_OFF_TILES = 1024;
constexpr int T_SMEM_TOTAL = T_OFF_TILES + 4 * BUF_BYTES;   // 164864

#if HAS_TC
// idesc: f32 accum, bf16 A/B, N=256 per issue, M=128
constexpr uint32_t T_IDESC =
    (1u << 4) | (1u << 7) | (1u << 10) | ((256 / 8) << 17) | ((TBM / 16) << 24);

__device__ __forceinline__ uint32_t elect_one_pred() {
    uint32_t pred;
    asm volatile("{\n\t.reg .pred p;\n\telect.sync _|p, 0xFFFFFFFF;\n\t"
                 "selp.b32 %0, 1, 0, p;\n\t}" : "=r"(pred));
    return pred;
}
#define MBARRIER_INIT(addr, cnt) \
    asm volatile("mbarrier.init.shared.b64 [%0], %1;" :: "r"(addr), "r"(cnt) : "memory")
#define MBAR_WAIT(addr, parity) do {                                          \
    uint32_t _m = (addr), _p = (parity);                                      \
    asm volatile("{\n\t.reg .pred P1;\n\t"                                    \
        "WAIT_LOOP_%=:\n\t"                                                   \
        "mbarrier.try_wait.parity.acquire.cta.shared::cta.b64 P1, [%0], %1, 0x989680;\n\t" \
        "@P1 bra.uni WAIT_DONE_%=;\n\t"                                       \
        "bra.uni WAIT_LOOP_%=;\n\t"                                           \
        "WAIT_DONE_%=:\n\t}" :: "r"(_m), "r"(_p) : "memory");                 \
} while (0)
#define TCGEN05_ALLOC(smem_addr, n) \
    asm volatile("tcgen05.alloc.cta_group::1.sync.aligned.shared::cta.b32 [%0], %1;" \
                 :: "r"(smem_addr), "r"((uint32_t)(n)) : "memory")
#define TCGEN05_DEALLOC(tmem, n) \
    asm volatile("tcgen05.dealloc.cta_group::1.sync.aligned.b32 %0, %1;" \
                 :: "r"(tmem), "r"((uint32_t)(n)))
#define TCGEN05_RELINQ() \
    asm volatile("tcgen05.relinquish_alloc_permit.cta_group::1.sync.aligned;")
#define TCGEN05_COMMIT(mbar) \
    asm volatile("tcgen05.commit.cta_group::1.mbarrier::arrive::one.shared::cluster.b64 [%0];" \
                 :: "r"(mbar) : "memory")
#define TCGEN05_FENCE_AFTER() \
    asm volatile("tcgen05.fence::after_thread_sync;" ::: "memory")
#define TCGEN05_FENCE_BEFORE() \
    asm volatile("tcgen05.fence::before_thread_sync;" ::: "memory")
#define TCGEN05_WAIT_LD() \
    asm volatile("tcgen05.wait::ld.sync.aligned;" ::: "memory")
#define FENCE_ASYNC_SHARED() \
    asm volatile("fence.proxy.async.shared::cta;" ::: "memory")
#define MMA_BF16_SS(dtmem, adesc, bdesc, idesc, enable) do {                  \
    uint32_t _e = (enable); uint32_t _z = 0;                                  \
    asm volatile("{\n\t.reg .pred p;\n\tsetp.ne.u32 p, %5, 0;\n\t"            \
        "tcgen05.mma.cta_group::1.kind::f16 [%0], %1, %2, %3, {%4,%4,%4,%4}, p;\n\t}" \
        :: "r"(dtmem), "l"(adesc), "l"(bdesc), "r"(idesc), "r"(_z), "r"(_e)   \
        : "memory");                                                          \
} while (0)
#define TCGEN05_LD_X32(r, tmem_addr) \
    asm volatile( \
        "tcgen05.ld.sync.aligned.32x32b.x32.b32 " \
        "{%0, %1, %2, %3, %4, %5, %6, %7, %8, %9, %10, %11, %12, %13, %14, %15, " \
        " %16, %17, %18, %19, %20, %21, %22, %23, %24, %25, %26, %27, %28, %29, %30, %31}, [%32];" \
        : "=r"((r)[0]),  "=r"((r)[1]),  "=r"((r)[2]),  "=r"((r)[3]),  \
          "=r"((r)[4]),  "=r"((r)[5]),  "=r"((r)[6]),  "=r"((r)[7]),  \
          "=r"((r)[8]),  "=r"((r)[9]),  "=r"((r)[10]), "=r"((r)[11]), \
          "=r"((r)[12]), "=r"((r)[13]), "=r"((r)[14]), "=r"((r)[15]), \
          "=r"((r)[16]), "=r"((r)[17]), "=r"((r)[18]), "=r"((r)[19]), \
          "=r"((r)[20]), "=r"((r)[21]), "=r"((r)[22]), "=r"((r)[23]), \
          "=r"((r)[24]), "=r"((r)[25]), "=r"((r)[26]), "=r"((r)[27]), \
          "=r"((r)[28]), "=r"((r)[29]), "=r"((r)[30]), "=r"((r)[31]) \
        : "r"(tmem_addr))

// K-major SW32 descriptor: layout=6, version=1, SBO=16 (8 rows x 32B = 256B/16),
// LBO=1 (16B). Same family as the proven SW128 desc (layout=2, SBO=64, LBO=1).
static constexpr uint64_t DESC_BASE_SW32 =
    (uint64_t(6) << 61) | (uint64_t(1) << 46) | (uint64_t(16) << 32) | (uint64_t(1) << 16);
__device__ __forceinline__ uint64_t make_desc32(uint32_t addr) {
    return DESC_BASE_SW32 | ((uint64_t)(addr >> 4) & 0x3FFF);
}
// SW32 store swizzle on byte offset within tile (32B rows)
__device__ __forceinline__ uint32_t sw32(uint32_t off) {
    return off ^ ((off >> 3) & 0x10);
}
#endif  // HAS_TC

template <int STAGE>
__global__ void __launch_bounds__(256, 1) gemm_tc(const float* __restrict__ bias,
                                                  float* __restrict__ out) {
#if HAS_TC
    extern __shared__ char smem[];
    uint32_t sb = smem_u32(smem);
    const int tid = threadIdx.x;
    const int wid = tid >> 5, lid = tid & 31;
    const int z  = blockIdx.z;
    const int m0 = blockIdx.y * TBM;        // n0 = 0: full N=512 per CTA

    const __nv_bfloat16 *Ahi, *Alo, *Bhi, *Blo;
    if (STAGE == 1) {
        Ahi = g_xhi  + (size_t)z * Np * Dd;  Alo = g_xlo  + (size_t)z * Np * Dd;
        Bhi = g_wthi;                        Blo = g_wtlo;
    } else {
        Ahi = g_xwhi + (size_t)z * Np * Dd;  Alo = g_xwlo + (size_t)z * Np * Dd;
        Bhi = g_xhi  + (size_t)z * Np * Dd;  Blo = g_xlo  + (size_t)z * Np * Dd;
    }

    if (tid == 0) {
        #pragma unroll
        for (int s = 0; s < 4; s++) MBARRIER_INIT(sb + T_OFF_MBAR + s * 8, 1);
    }
    if (wid == 0) TCGEN05_ALLOC(sb, 512);
    __syncthreads();
    uint32_t tmem;
    asm volatile("ld.shared.b32 %0, [%1];" : "=r"(tmem) : "r"(sb));
    if (wid == 0) TCGEN05_RELINQ();

    // Load K=16 slice h of all four tiles into buffer h&3 (one commit group).
    auto load_iter = [&](int h) {
        uint32_t buf = sb + T_OFF_TILES + (h & 3) * BUF_BYTES;
        const size_t kb = (size_t)h * 32;        // K byte offset (16 bf16)
        // A hi/lo: 128 rows x 32B = 256 chunks -> 1/thread each
        {
            int row = tid >> 1;
            int c   = (tid & 1) * 16;
            uint32_t soff = sw32(row * 32 + c);
            size_t goff = (size_t)(m0 + row) * 1024 + kb + c;
            cp_async16(buf + soff,       reinterpret_cast<const char*>(Ahi) + goff);
            cp_async16(buf + A_T + soff, reinterpret_cast<const char*>(Alo) + goff);
        }
        // B hi/lo: 512 rows x 32B = 1024 chunks -> 4/thread each
        {
            uint32_t bb = buf + 2 * A_T;
            #pragma unroll
            for (int i = 0; i < 4; i++) {
                int chunk = tid + i * 256;
                int row = chunk >> 1;
                int c   = (chunk & 1) * 16;
                uint32_t soff = sw32(row * 32 + c);
                size_t goff = (size_t)row * 1024 + kb + c;
                cp_async16(bb + soff,       reinterpret_cast<const char*>(Bhi) + goff);
                cp_async16(bb + B_T + soff, reinterpret_cast<const char*>(Blo) + goff);
            }
        }
        CP_COMMIT();
    };

    load_iter(0);
    load_iter(1);
    load_iter(2);

    for (int h = 0; h < NITER; h++) {
        if (h <= NITER - 3)      { CP_WAIT(2); }
        else if (h == NITER - 2) { CP_WAIT(1); }
        else                     { CP_WAIT(0); }
        FENCE_ASYNC_SHARED();
        __syncthreads();   // buffer h&3 fully loaded for all threads

        if (wid == 0) {
            uint32_t buf = sb + T_OFF_TILES + (h & 3) * BUF_BYTES;
            uint64_t dAh = make_desc32(buf);
            uint64_t dAl = make_desc32(buf + A_T);
            uint64_t dBh = make_desc32(buf + 2 * A_T);
            uint64_t dBl = make_desc32(buf + 2 * A_T + B_T);
            if (elect_one_pred()) {
                #pragma unroll
                for (int nh = 0; nh < 2; nh++) {
                    // B rows [nh*256, nh*256+256): byte offset nh*256*32 -> /16
                    uint64_t doff = (uint64_t)(nh * 512);
                    uint32_t tm = tmem + nh * 256;
                    MMA_BF16_SS(tm, dAh, dBh + doff, T_IDESC, h > 0 ? 1u : 0u);
                    MMA_BF16_SS(tm, dAh, dBl + doff, T_IDESC, 1u);
                    MMA_BF16_SS(tm, dAl, dBh + doff, T_IDESC, 1u);
                }
                TCGEN05_COMMIT(sb + T_OFF_MBAR + (h & 3) * 8);
            }
        }

        if (h + 3 < NITER) {
            // buffer (h+3)&3 == (h-1)&3: wait its MMAs drained before refill
            if (h >= 1)
                MBAR_WAIT(sb + T_OFF_MBAR + ((h - 1) & 3) * 8, ((h - 1) >> 2) & 1);
            load_iter(h + 3);
        }
    }

    MBAR_WAIT(sb + T_OFF_MBAR + ((NITER - 1) & 3) * 8, ((NITER - 1) >> 2) & 1);
    TCGEN05_FENCE_AFTER();

    // Epilogue: warp w -> rows m0+(w&3)*32+lid, cols [(w>>2)*256, +256)
    {
        const int gi   = m0 + (wid & 3) * 32 + lid;
        const int wcol = (wid >> 2) * 256;
        if (STAGE == 1) {
            size_t base = ((size_t)z * Np + gi) * Dd + wcol;
            #pragma unroll
            for (int c0 = 0; c0 < 256; c0 += 32) {
                uint32_t r[32];
                TCGEN05_LD_X32(r, tmem + wcol + c0);
                TCGEN05_WAIT_LD();
                __align__(16) __nv_bfloat16 hs[32], ls[32];
                #pragma unroll
                for (int c = 0; c < 32; c++) {
                    float v = __uint_as_float(r[c]);
                    __nv_bfloat16 hh = __float2bfloat16_rn(v);
                    hs[c] = hh;
                    ls[c] = __float2bfloat16_rn(v - __bfloat162float(hh));
                }
                uint4* dh = reinterpret_cast<uint4*>(g_xwhi + base + c0);
                uint4* dl = reinterpret_cast<uint4*>(g_xwlo + base + c0);
                const uint4* sh = reinterpret_cast<const uint4*>(hs);
                const uint4* sl = reinterpret_cast<const uint4*>(ls);
                #pragma unroll
                for (int q = 0; q < 4; q++) { dh[q] = sh[q]; dl[q] = sl[q]; }
            }
        } else {
            const float bv = *bias;
            size_t base = ((size_t)z * Np + gi) * Np + wcol;
            #pragma unroll
            for (int c0 = 0; c0 < 256; c0 += 32) {
                uint32_t r[32];
                TCGEN05_LD_X32(r, tmem + wcol + c0);
                TCGEN05_WAIT_LD();
                __align__(16) float vs[32];
                #pragma unroll
                for (int c = 0; c < 32; c++) {
                    int gj = wcol + c0 + c;
                    float v = __uint_as_float(r[c]) + bv;
                    vs[c] = (gi == gj) ? 0.0f : v;
                }
                float4* d = reinterpret_cast<float4*>(out + base + c0);
                const float4* s = reinterpret_cast<const float4*>(vs);
                #pragma unroll
                for (int q = 0; q < 8; q++) d[q] = s[q];
            }
        }
        TCGEN05_FENCE_BEFORE();
    }
    __syncthreads();
    if (wid == 0) TCGEN05_DEALLOC(tmem, 512);
#endif  // HAS_TC
}

// ---------------------------------------------------------------------------
extern "C" void kernel_launch(void* const* d_in, const int* in_sizes, int n_in,
                              void* d_out, int out_size) {
    const float* X    = (const float*)d_in[0];   // (32, 512, 512)
    const float* W    = (const float*)d_in[1];   // (512, 512)
    const float* bias = (const float*)d_in[2];   // scalar
    float* out = (float*)d_out;                  // (32, 512, 512)

    cudaFuncSetAttribute(gemm_tc<1>, cudaFuncAttributeMaxDynamicSharedMemorySize, T_SMEM_TOTAL);
    cudaFuncSetAttribute(gemm_tc<2>, cudaFuncAttributeMaxDynamicSharedMemorySize, T_SMEM_TOTAL);

    conv_x_kernel<<<(Bb * Np * Dd) / 4 / 256, 256>>>((const float4*)X);
    conv_w_kernel<<<dim3(16, 16), dim3(32, 8)>>>(W);

    dim3 grid(1, Np / TBM, Bb);   // (1, 4, 32) = 128 CTAs — single wave
    gemm_tc<1><<<grid, 256, T_SMEM_TOTAL>>>(bias, out);
    gemm_tc<2><<<grid, 256, T_SMEM_TOTAL>>>(bias, out);
}

// round 9
// speedup vs baseline: 1.1927x; 1.1927x over previous
#include <cuda_runtime.h>
#include <cuda_bf16.h>
#include <cstdint>

// tcgen05 exists only in the compute_103a pass; plain sm_103 compiles empty stubs.
#if defined(__CUDA_ARCH__) && defined(__CUDA_ARCH_FEAT_SM103_ALL)
#define HAS_TC 1
#else
#define HAS_TC 0
#endif

constexpr int Bb = 32, Np = 512, Dd = 512;

// ---------------- scratch (__device__ globals; alloc-free rule) -------------
__device__ __align__(16) __nv_bfloat16 g_xhi [(size_t)Bb * Np * Dd];
__device__ __align__(16) __nv_bfloat16 g_xlo [(size_t)Bb * Np * Dd];
__device__ __align__(16) __nv_bfloat16 g_wthi[(size_t)Dd * Dd];
__device__ __align__(16) __nv_bfloat16 g_wtlo[(size_t)Dd * Dd];
__device__ __align__(16) __nv_bfloat16 g_xwhi[(size_t)Bb * Np * Dd];
__device__ __align__(16) __nv_bfloat16 g_xwlo[(size_t)Bb * Np * Dd];

// ---------------- common helpers -------------------------------------------
__device__ __forceinline__ uint32_t smem_u32(const void* p) {
    uint32_t a;
    asm("{ .reg .u64 t; cvta.to.shared.u64 t, %1; cvt.u32.u64 %0, t; }"
        : "=r"(a) : "l"(p));
    return a;
}
__device__ __forceinline__ void cp_async16(uint32_t dst, const void* src) {
    asm volatile("cp.async.cg.shared.global [%0], [%1], 16;"
                 :: "r"(dst), "l"(src));
}
#define CP_COMMIT()  asm volatile("cp.async.commit_group;" ::: "memory")
#define CP_WAIT(n)   asm volatile("cp.async.wait_group %0;" :: "n"(n) : "memory")

// ---------------- conversion kernels ---------------------------------------
__global__ __launch_bounds__(256) void conv_x_kernel(const float4* __restrict__ X) {
    size_t i = (size_t)blockIdx.x * 256 + threadIdx.x;
    float4 v = X[i];
    union { __nv_bfloat16 b[4]; uint2 u; } H, L;
    const float* f = &v.x;
    #pragma unroll
    for (int j = 0; j < 4; j++) {
        __nv_bfloat16 h = __float2bfloat16_rn(f[j]);
        H.b[j] = h;
        L.b[j] = __float2bfloat16_rn(f[j] - __bfloat162float(h));
    }
    reinterpret_cast<uint2*>(g_xhi)[i] = H.u;
    reinterpret_cast<uint2*>(g_xlo)[i] = L.u;
}

__global__ __launch_bounds__(256) void conv_w_kernel(const float* __restrict__ W) {
    __shared__ float t[32][33];
    int tx = threadIdx.x, ty = threadIdx.y;          // 32 x 8
    int bx = blockIdx.x * 32, by = blockIdx.y * 32;  // bx: n-block, by: k-block
    #pragma unroll
    for (int r = 0; r < 4; r++)
        t[ty + r * 8][tx] = W[(size_t)(by + ty + r * 8) * Dd + bx + tx];
    __syncthreads();
    #pragma unroll
    for (int r = 0; r < 4; r++) {
        int n = bx + ty + r * 8, kk = by + tx;
        float v = t[tx][ty + r * 8];                  // = W[kk][n]
        __nv_bfloat16 h = __float2bfloat16_rn(v);
        g_wthi[(size_t)n * Dd + kk] = h;
        g_wtlo[(size_t)n * Dd + kk] = __float2bfloat16_rn(v - __bfloat162float(h));
    }
}

// ===========================================================================
// tcgen05 bf16x3 GEMM, 128(M) x 256(N), warp-specialized:
//   warp 0          = MMA consumer (mbarrier-paced, no CTA barriers in loop)
//   warps 2-7 (192) = cp.async producers, per-thread group self-tracking
// K pipelined in 16 halves of K=32 over 4 half-buffers (2 x 96KB SW128 stages).
// ===========================================================================
constexpr int TBM = 128, TBN = 256;
constexpr int NHALF = 16;                            // 512 / 32
constexpr int A_TILE_BYTES = TBM * 64 * 2;           // 16384
constexpr int B_TILE_BYTES = TBN * 64 * 2;           // 32768
constexpr int T_STAGE_BYTES = 2 * A_TILE_BYTES + 2 * B_TILE_BYTES;  // 98304
constexpr int T_OFF_MBAR  = 8;                       // full[0..3], empty[0..3]
constexpr int T_OFF_TILES = 1024;
constexpr int T_SMEM_TOTAL = T_OFF_TILES + 2 * T_STAGE_BYTES;       // 197632
constexpr int NPROD = 192;                           // producer threads

#if HAS_TC
constexpr uint32_t T_IDESC =
    (1u << 4) | (1u << 7) | (1u << 10) | ((TBN / 8) << 17) | ((TBM / 16) << 24);

__device__ __forceinline__ uint32_t elect_one_pred() {
    uint32_t pred;
    asm volatile("{\n\t.reg .pred p;\n\telect.sync _|p, 0xFFFFFFFF;\n\t"
                 "selp.b32 %0, 1, 0, p;\n\t}" : "=r"(pred));
    return pred;
}
#define MBARRIER_INIT(addr, cnt) \
    asm volatile("mbarrier.init.shared.b64 [%0], %1;" :: "r"(addr), "r"(cnt) : "memory")
#define MBARRIER_ARRIVE(addr) \
    asm volatile("mbarrier.arrive.shared.b64 _, [%0];" :: "r"(addr) : "memory")
#define MBAR_WAIT(addr, parity) do {                                          \
    uint32_t _m = (addr), _p = (parity);                                      \
    asm volatile("{\n\t.reg .pred P1;\n\t"                                    \
        "WAIT_LOOP_%=:\n\t"                                                   \
        "mbarrier.try_wait.parity.acquire.cta.shared::cta.b64 P1, [%0], %1, 0x989680;\n\t" \
        "@P1 bra.uni WAIT_DONE_%=;\n\t"                                       \
        "bra.uni WAIT_LOOP_%=;\n\t"                                           \
        "WAIT_DONE_%=:\n\t}" :: "r"(_m), "r"(_p) : "memory");                 \
} while (0)
#define TCGEN05_ALLOC(smem_addr, n) \
    asm volatile("tcgen05.alloc.cta_group::1.sync.aligned.shared::cta.b32 [%0], %1;" \
                 :: "r"(smem_addr), "r"((uint32_t)(n)) : "memory")
#define TCGEN05_DEALLOC(tmem, n) \
    asm volatile("tcgen05.dealloc.cta_group::1.sync.aligned.b32 %0, %1;" \
                 :: "r"(tmem), "r"((uint32_t)(n)))
#define TCGEN05_RELINQ() \
    asm volatile("tcgen05.relinquish_alloc_permit.cta_group::1.sync.aligned;")
#define TCGEN05_COMMIT(mbar) \
    asm volatile("tcgen05.commit.cta_group::1.mbarrier::arrive::one.shared::cluster.b64 [%0];" \
                 :: "r"(mbar) : "memory")
#define TCGEN05_FENCE_AFTER() \
    asm volatile("tcgen05.fence::after_thread_sync;" ::: "memory")
#define TCGEN05_FENCE_BEFORE() \
    asm volatile("tcgen05.fence::before_thread_sync;" ::: "memory")
#define TCGEN05_WAIT_LD() \
    asm volatile("tcgen05.wait::ld.sync.aligned;" ::: "memory")
#define FENCE_ASYNC_SHARED() \
    asm volatile("fence.proxy.async.shared::cta;" ::: "memory")
#define MMA_BF16_SS(dtmem, adesc, bdesc, idesc, enable) do {                  \
    uint32_t _e = (enable); uint32_t _z = 0;                                  \
    asm volatile("{\n\t.reg .pred p;\n\tsetp.ne.u32 p, %5, 0;\n\t"            \
        "tcgen05.mma.cta_group::1.kind::f16 [%0], %1, %2, %3, {%4,%4,%4,%4}, p;\n\t}" \
        :: "r"(dtmem), "l"(adesc), "l"(bdesc), "r"(idesc), "r"(_z), "r"(_e)   \
        : "memory");                                                          \
} while (0)
#define TCGEN05_LD_X32(r, tmem_addr) \
    asm volatile( \
        "tcgen05.ld.sync.aligned.32x32b.x32.b32 " \
        "{%0, %1, %2, %3, %4, %5, %6, %7, %8, %9, %10, %11, %12, %13, %14, %15, " \
        " %16, %17, %18, %19, %20, %21, %22, %23, %24, %25, %26, %27, %28, %29, %30, %31}, [%32];" \
        : "=r"((r)[0]),  "=r"((r)[1]),  "=r"((r)[2]),  "=r"((r)[3]),  \
          "=r"((r)[4]),  "=r"((r)[5]),  "=r"((r)[6]),  "=r"((r)[7]),  \
          "=r"((r)[8]),  "=r"((r)[9]),  "=r"((r)[10]), "=r"((r)[11]), \
          "=r"((r)[12]), "=r"((r)[13]), "=r"((r)[14]), "=r"((r)[15]), \
          "=r"((r)[16]), "=r"((r)[17]), "=r"((r)[18]), "=r"((r)[19]), \
          "=r"((r)[20]), "=r"((r)[21]), "=r"((r)[22]), "=r"((r)[23]), \
          "=r"((r)[24]), "=r"((r)[25]), "=r"((r)[26]), "=r"((r)[27]), \
          "=r"((r)[28]), "=r"((r)[29]), "=r"((r)[30]), "=r"((r)[31]) \
        : "r"(tmem_addr))

static constexpr uint64_t DESC_BASE_SW128 =
    (uint64_t(2) << 61) | (uint64_t(1) << 46) | (uint64_t(64) << 32) | (uint64_t(1) << 16);
__device__ __forceinline__ uint64_t make_desc(uint32_t addr) {
    return DESC_BASE_SW128 | ((uint64_t)(addr >> 4) & 0x3FFF);
}
#endif  // HAS_TC

template <int STAGE>
__global__ void __launch_bounds__(256, 1) gemm_tc(const float* __restrict__ bias,
                                                  float* __restrict__ out) {
#if HAS_TC
    extern __shared__ char smem[];
    uint32_t sb = smem_u32(smem);
    const int tid = threadIdx.x;
    const int wid = tid >> 5, lid = tid & 31;
    const int z  = blockIdx.z;
    const int m0 = blockIdx.y * TBM, n0 = blockIdx.x * TBN;

    const __nv_bfloat16 *Ahi, *Alo, *Bhi, *Blo;
    if (STAGE == 1) {
        Ahi = g_xhi  + (size_t)z * Np * Dd;  Alo = g_xlo  + (size_t)z * Np * Dd;
        Bhi = g_wthi;                        Blo = g_wtlo;
    } else {
        Ahi = g_xwhi + (size_t)z * Np * Dd;  Alo = g_xwlo + (size_t)z * Np * Dd;
        Bhi = g_xhi  + (size_t)z * Np * Dd;  Blo = g_xlo  + (size_t)z * Np * Dd;
    }

    const uint32_t full0  = sb + T_OFF_MBAR;        // full[s]  = +s*8
    const uint32_t empty0 = sb + T_OFF_MBAR + 32;   // empty[s] = +32+s*8

    if (tid == 0) {
        #pragma unroll
        for (int s = 0; s < 4; s++) {
            MBARRIER_INIT(full0  + s * 8, NPROD);   // one arrive per producer
            MBARRIER_INIT(empty0 + s * 8, 1);       // tcgen05.commit arrive
        }
    }
    if (wid == 0) TCGEN05_ALLOC(sb, 256);
    __syncthreads();
    uint32_t tmem;
    asm volatile("ld.shared.b32 %0, [%1];" : "=r"(tmem) : "r"(sb));
    if (wid == 0) TCGEN05_RELINQ();
    __syncthreads();   // barriers + tmem visible everywhere before the race starts

    if (wid >= 2) {
        // ---------------- producers: warps 2-7 (192 threads) ----------------
        const int ptid = tid - 64;   // 0..191
        auto load_half = [&](int h) {
            uint32_t stg = sb + T_OFF_TILES + ((h >> 1) & 1) * T_STAGE_BYTES;
            const int coloff = (h & 1) * 64;
            const size_t kb = (size_t)h * 64;
            #pragma unroll
            for (int i = 0; i < 16; i++) {
                int chunk = ptid + i * NPROD;   // 0..3071
                if (chunk < 1024) {             // A hi (0..511) / A lo (512..1023)
                    int local = chunk & 511;
                    const char* src = reinterpret_cast<const char*>(chunk < 512 ? Ahi : Alo);
                    uint32_t tb = stg + (chunk < 512 ? 0 : A_TILE_BYTES);
                    int row = local >> 2, c = (local & 3) * 16;
                    uint32_t soff = row * 128 + ((coloff + c) ^ ((row & 7) << 4));
                    cp_async16(tb + soff, src + (size_t)(m0 + row) * 1024 + kb + c);
                } else {                        // B hi (1024..2047) / B lo (2048..3071)
                    int local = (chunk - 1024) & 1023;
                    const char* src = reinterpret_cast<const char*>(chunk < 2048 ? Bhi : Blo);
                    uint32_t tb = stg + 2 * A_TILE_BYTES + (chunk < 2048 ? 0 : B_TILE_BYTES);
                    int row = local >> 2, c = (local & 3) * 16;
                    uint32_t soff = row * 128 + ((coloff + c) ^ ((row & 7) << 4));
                    cp_async16(tb + soff, src + (size_t)(n0 + row) * 1024 + kb + c);
                }
            }
            CP_COMMIT();
        };

        for (int h = 0; h < NHALF; h++) {
            if (h >= 4)   // buffer h&3 reused: MMA of half h-4 must have drained
                MBAR_WAIT(empty0 + (h & 3) * 8, ((h - 4) >> 2) & 1);
            load_half(h);
            if (h >= 2) { // this thread's group h-2 has landed once <=2 newer remain
                CP_WAIT(2);
                FENCE_ASYNC_SHARED();
                MBARRIER_ARRIVE(full0 + ((h - 2) & 3) * 8);
            }
        }
        CP_WAIT(1); FENCE_ASYNC_SHARED();
        MBARRIER_ARRIVE(full0 + ((NHALF - 2) & 3) * 8);
        CP_WAIT(0); FENCE_ASYNC_SHARED();
        MBARRIER_ARRIVE(full0 + ((NHALF - 1) & 3) * 8);
    } else if (wid == 0) {
        // ---------------- MMA consumer: warp 0 ------------------------------
        for (int h = 0; h < NHALF; h++) {
            MBAR_WAIT(full0 + (h & 3) * 8, (h >> 2) & 1);
            uint32_t stg = sb + T_OFF_TILES + ((h >> 1) & 1) * T_STAGE_BYTES;
            uint64_t dAh = make_desc(stg);
            uint64_t dAl = make_desc(stg + A_TILE_BYTES);
            uint64_t dBh = make_desc(stg + 2 * A_TILE_BYTES);
            uint64_t dBl = make_desc(stg + 2 * A_TILE_BYTES + B_TILE_BYTES);
            if (elect_one_pred()) {
                const uint64_t hoff = (uint64_t)((h & 1) * 4);
                #pragma unroll
                for (int s = 0; s < 2; s++) {             // two K=16 steps
                    uint64_t o = hoff + (uint64_t)(s * 2);
                    MMA_BF16_SS(tmem, dAh + o, dBh + o, T_IDESC, (h == 0 && s == 0) ? 0u : 1u);
                    MMA_BF16_SS(tmem, dAh + o, dBl + o, T_IDESC, 1u);
                    MMA_BF16_SS(tmem, dAl + o, dBh + o, T_IDESC, 1u);
                }
                TCGEN05_COMMIT(empty0 + (h & 3) * 8);
            }
        }
        // last half (15): 4th completion on empty[3] -> wait parity 1
        MBAR_WAIT(empty0 + 3 * 8, 1);
    }
    // (warp 1 idles through the mainloop)

    __syncthreads();            // everyone sees the final accumulator
    TCGEN05_FENCE_AFTER();

    // Epilogue: 8 warps. Warps 0-3 -> cols [0,128), warps 4-7 -> cols [128,256).
    {
        const int half = wid >> 2;
        const int gi   = m0 + (wid & 3) * 32 + lid;
        const int cbase = half * 128;
        if (STAGE == 1) {
            size_t base = ((size_t)z * Np + gi) * Dd + n0 + cbase;
            #pragma unroll
            for (int c0 = 0; c0 < 128; c0 += 32) {
                uint32_t r[32];
                TCGEN05_LD_X32(r, tmem + cbase + c0);
                TCGEN05_WAIT_LD();
                __align__(16) __nv_bfloat16 hs[32], ls[32];
                #pragma unroll
                for (int c = 0; c < 32; c++) {
                    float v = __uint_as_float(r[c]);
                    __nv_bfloat16 hh = __float2bfloat16_rn(v);
                    hs[c] = hh;
                    ls[c] = __float2bfloat16_rn(v - __bfloat162float(hh));
                }
                uint4* dh = reinterpret_cast<uint4*>(g_xwhi + base + c0);
                uint4* dl = reinterpret_cast<uint4*>(g_xwlo + base + c0);
                const uint4* sh = reinterpret_cast<const uint4*>(hs);
                const uint4* sl = reinterpret_cast<const uint4*>(ls);
                #pragma unroll
                for (int q = 0; q < 4; q++) { dh[q] = sh[q]; dl[q] = sl[q]; }
            }
        } else {
            const float bv = *bias;
            size_t base = ((size_t)z * Np + gi) * Np + n0 + cbase;
            #pragma unroll
            for (int c0 = 0; c0 < 128; c0 += 32) {
                uint32_t r[32];
                TCGEN05_LD_X32(r, tmem + cbase + c0);
                TCGEN05_WAIT_LD();
                __align__(16) float vs[32];
                #pragma unroll
                for (int c = 0; c < 32; c++) {
                    int gj = n0 + cbase + c0 + c;
                    float v = __uint_as_float(r[c]) + bv;
                    vs[c] = (gi == gj) ? 0.0f : v;
                }
                float4* d = reinterpret_cast<float4*>(out + base + c0);
                const float4* s = reinterpret_cast<const float4*>(vs);
                #pragma unroll
                for (int q = 0; q < 8; q++) d[q] = s[q];
            }
        }
        TCGEN05_FENCE_BEFORE();
    }
    __syncthreads();
    if (wid == 0) TCGEN05_DEALLOC(tmem, 256);
#endif  // HAS_TC
}

// ---------------------------------------------------------------------------
extern "C" void kernel_launch(void* const* d_in, const int* in_sizes, int n_in,
                              void* d_out, int out_size) {
    const float* X    = (const float*)d_in[0];   // (32, 512, 512)
    const float* W    = (const float*)d_in[1];   // (512, 512)
    const float* bias = (const float*)d_in[2];   // scalar
    float* out = (float*)d_out;                  // (32, 512, 512)

    cudaFuncSetAttribute(gemm_tc<1>, cudaFuncAttributeMaxDynamicSharedMemorySize, T_SMEM_TOTAL);
    cudaFuncSetAttribute(gemm_tc<2>, cudaFuncAttributeMaxDynamicSharedMemorySize, T_SMEM_TOTAL);

    conv_w_kernel<<<dim3(16, 16), dim3(32, 8)>>>(W);
    conv_x_kernel<<<(Bb * Np * Dd) / 4 / 256, 256>>>((const float4*)X);

    dim3 grid(Np / TBN, Np / TBM, Bb);   // (2, 4, 32) = 256 CTAs
    gemm_tc<1><<<grid, 256, T_SMEM_TOTAL>>>(bias, out);
    gemm_tc<2><<<grid, 256, T_SMEM_TOTAL>>>(bias, out);
}

// round 10
// speedup vs baseline: 1.3517x; 1.1334x over previous
#include <cuda_runtime.h>
#include <cuda.h>
#include <cuda_bf16.h>
#include <cstdint>

// tcgen05 exists only in the compute_103a pass; plain sm_103 compiles empty stubs.
#if defined(__CUDA_ARCH__) && defined(__CUDA_ARCH_FEAT_SM103_ALL)
#define HAS_TC 1
#else
#define HAS_TC 0
#endif

constexpr int Bb = 32, Np = 512, Dd = 512;

// ---------------- scratch (__device__ globals; alloc-free rule) -------------
__device__ __align__(1024) __nv_bfloat16 g_xhi [(size_t)Bb * Np * Dd];
__device__ __align__(1024) __nv_bfloat16 g_xlo [(size_t)Bb * Np * Dd];
__device__ __align__(1024) __nv_bfloat16 g_wthi[(size_t)Dd * Dd];
__device__ __align__(1024) __nv_bfloat16 g_wtlo[(size_t)Dd * Dd];
__device__ __align__(1024) __nv_bfloat16 g_xwhi[(size_t)Bb * Np * Dd];
__device__ __align__(1024) __nv_bfloat16 g_xwlo[(size_t)Bb * Np * Dd];

// ---------------- common helpers -------------------------------------------
__device__ __forceinline__ uint32_t smem_u32(const void* p) {
    uint32_t a;
    asm("{ .reg .u64 t; cvta.to.shared.u64 t, %1; cvt.u32.u64 %0, t; }"
        : "=r"(a) : "l"(p));
    return a;
}

// ---------------- conversion kernels ---------------------------------------
__global__ __launch_bounds__(256) void conv_x_kernel(const float4* __restrict__ X) {
    size_t i = (size_t)blockIdx.x * 256 + threadIdx.x;
    float4 v = X[i];
    union { __nv_bfloat16 b[4]; uint2 u; } H, L;
    const float* f = &v.x;
    #pragma unroll
    for (int j = 0; j < 4; j++) {
        __nv_bfloat16 h = __float2bfloat16_rn(f[j]);
        H.b[j] = h;
        L.b[j] = __float2bfloat16_rn(f[j] - __bfloat162float(h));
    }
    reinterpret_cast<uint2*>(g_xhi)[i] = H.u;
    reinterpret_cast<uint2*>(g_xlo)[i] = L.u;
}

__global__ __launch_bounds__(256) void conv_w_kernel(const float* __restrict__ W) {
    __shared__ float t[32][33];
    int tx = threadIdx.x, ty = threadIdx.y;          // 32 x 8
    int bx = blockIdx.x * 32, by = blockIdx.y * 32;  // bx: n-block, by: k-block
    #pragma unroll
    for (int r = 0; r < 4; r++)
        t[ty + r * 8][tx] = W[(size_t)(by + ty + r * 8) * Dd + bx + tx];
    __syncthreads();
    #pragma unroll
    for (int r = 0; r < 4; r++) {
        int n = bx + ty + r * 8, kk = by + tx;
        float v = t[tx][ty + r * 8];                  // = W[kk][n]
        __nv_bfloat16 h = __float2bfloat16_rn(v);
        g_wthi[(size_t)n * Dd + kk] = h;
        g_wtlo[(size_t)n * Dd + kk] = __float2bfloat16_rn(v - __bfloat162float(h));
    }
}

// ===========================================================================
// tcgen05 bf16x3 GEMM, 128(M) x 256(N), TMA-fed:
//   warp 0 (converged) drives TMA loads + MMAs via mbarriers; warps 1-7 idle
//   until the epilogue. 2 stages of K=64 (96 KB each), 8 k-iterations.
// ===========================================================================
constexpr int TBM = 128, TBN = 256;
constexpr int T_KITERS = Dd / 64;                    // 8
constexpr int A_TILE_BYTES = TBM * 64 * 2;           // 16384
constexpr int B_TILE_BYTES = TBN * 64 * 2;           // 32768
constexpr int T_STAGE_BYTES = 2 * A_TILE_BYTES + 2 * B_TILE_BYTES;  // 98304
constexpr int T_OFF_MBAR  = 8;                       // full[0..1], empty[0..1]
constexpr int T_OFF_TILES = 1024;
constexpr int T_SMEM_TOTAL = T_OFF_TILES + 2 * T_STAGE_BYTES;       // 197632

#if HAS_TC
constexpr uint32_t T_IDESC =
    (1u << 4) | (1u << 7) | (1u << 10) | ((TBN / 8) << 17) | ((TBM / 16) << 24);

__device__ __forceinline__ uint32_t elect_one_pred() {
    uint32_t pred;
    asm volatile("{\n\t.reg .pred p;\n\telect.sync _|p, 0xFFFFFFFF;\n\t"
                 "selp.b32 %0, 1, 0, p;\n\t}" : "=r"(pred));
    return pred;
}
#define MBARRIER_INIT(addr, cnt) \
    asm volatile("mbarrier.init.shared.b64 [%0], %1;" :: "r"(addr), "r"(cnt) : "memory")
#define MBARRIER_EXPECT_TX(addr, bytes) \
    asm volatile("mbarrier.arrive.expect_tx.shared.b64 _, [%0], %1;" \
                 :: "r"(addr), "r"((uint32_t)(bytes)) : "memory")
#define MBAR_WAIT(addr, parity) do {                                          \
    uint32_t _m = (addr), _p = (parity);                                      \
    asm volatile("{\n\t.reg .pred P1;\n\t"                                    \
        "WAIT_LOOP_%=:\n\t"                                                   \
        "mbarrier.try_wait.parity.acquire.cta.shared::cta.b64 P1, [%0], %1, 0x989680;\n\t" \
        "@P1 bra.uni WAIT_DONE_%=;\n\t"                                       \
        "bra.uni WAIT_LOOP_%=;\n\t"                                           \
        "WAIT_DONE_%=:\n\t}" :: "r"(_m), "r"(_p) : "memory");                 \
} while (0)
#define TMA_LOAD_2D(smem_addr, map_ptr, cx, cy, mbar) \
    asm volatile("cp.async.bulk.tensor.2d.shared::cta.global.tile.mbarrier::complete_tx::bytes " \
                 "[%0], [%1, {%2, %3}], [%4];" \
                 :: "r"(smem_addr), "l"(map_ptr), "r"(cx), "r"(cy), "r"(mbar) : "memory")
#define TCGEN05_ALLOC(smem_addr, n) \
    asm volatile("tcgen05.alloc.cta_group::1.sync.aligned.shared::cta.b32 [%0], %1;" \
                 :: "r"(smem_addr), "r"((uint32_t)(n)) : "memory")
#define TCGEN05_DEALLOC(tmem, n) \
    asm volatile("tcgen05.dealloc.cta_group::1.sync.aligned.b32 %0, %1;" \
                 :: "r"(tmem), "r"((uint32_t)(n)))
#define TCGEN05_RELINQ() \
    asm volatile("tcgen05.relinquish_alloc_permit.cta_group::1.sync.aligned;")
#define TCGEN05_COMMIT(mbar) \
    asm volatile("tcgen05.commit.cta_group::1.mbarrier::arrive::one.shared::cluster.b64 [%0];" \
                 :: "r"(mbar) : "memory")
#define TCGEN05_FENCE_AFTER() \
    asm volatile("tcgen05.fence::after_thread_sync;" ::: "memory")
#define TCGEN05_FENCE_BEFORE() \
    asm volatile("tcgen05.fence::before_thread_sync;" ::: "memory")
#define TCGEN05_WAIT_LD() \
    asm volatile("tcgen05.wait::ld.sync.aligned;" ::: "memory")
#define MMA_BF16_SS(dtmem, adesc, bdesc, idesc, enable) do {                  \
    uint32_t _e = (enable); uint32_t _z = 0;                                  \
    asm volatile("{\n\t.reg .pred p;\n\tsetp.ne.u32 p, %5, 0;\n\t"            \
        "tcgen05.mma.cta_group::1.kind::f16 [%0], %1, %2, %3, {%4,%4,%4,%4}, p;\n\t}" \
        :: "r"(dtmem), "l"(adesc), "l"(bdesc), "r"(idesc), "r"(_z), "r"(_e)   \
        : "memory");                                                          \
} while (0)
#define TCGEN05_LD_X32(r, tmem_addr) \
    asm volatile( \
        "tcgen05.ld.sync.aligned.32x32b.x32.b32 " \
        "{%0, %1, %2, %3, %4, %5, %6, %7, %8, %9, %10, %11, %12, %13, %14, %15, " \
        " %16, %17, %18, %19, %20, %21, %22, %23, %24, %25, %26, %27, %28, %29, %30, %31}, [%32];" \
        : "=r"((r)[0]),  "=r"((r)[1]),  "=r"((r)[2]),  "=r"((r)[3]),  \
          "=r"((r)[4]),  "=r"((r)[5]),  "=r"((r)[6]),  "=r"((r)[7]),  \
          "=r"((r)[8]),  "=r"((r)[9]),  "=r"((r)[10]), "=r"((r)[11]), \
          "=r"((r)[12]), "=r"((r)[13]), "=r"((r)[14]), "=r"((r)[15]), \
          "=r"((r)[16]), "=r"((r)[17]), "=r"((r)[18]), "=r"((r)[19]), \
          "=r"((r)[20]), "=r"((r)[21]), "=r"((r)[22]), "=r"((r)[23]), \
          "=r"((r)[24]), "=r"((r)[25]), "=r"((r)[26]), "=r"((r)[27]), \
          "=r"((r)[28]), "=r"((r)[29]), "=r"((r)[30]), "=r"((r)[31]) \
        : "r"(tmem_addr))

static constexpr uint64_t DESC_BASE_SW128 =
    (uint64_t(2) << 61) | (uint64_t(1) << 46) | (uint64_t(64) << 32) | (uint64_t(1) << 16);
__device__ __forceinline__ uint64_t make_desc(uint32_t addr) {
    return DESC_BASE_SW128 | ((uint64_t)(addr >> 4) & 0x3FFF);
}
#endif  // HAS_TC

template <int STAGE>
__global__ void __launch_bounds__(256, 1) gemm_tc(
    const float* __restrict__ bias, float* __restrict__ out,
    const __grid_constant__ CUtensorMap mAhi, const __grid_constant__ CUtensorMap mAlo,
    const __grid_constant__ CUtensorMap mBhi, const __grid_constant__ CUtensorMap mBlo)
{
#if HAS_TC
    extern __shared__ char smem[];
    uint32_t sb = smem_u32(smem);
    const int tid = threadIdx.x;
    const int wid = tid >> 5, lid = tid & 31;
    const int z  = blockIdx.z;
    const int m0 = blockIdx.y * TBM, n0 = blockIdx.x * TBN;

    // TMA row coordinates (y): A tensors are batched (Bb*Np rows); for STAGE 1
    // the B tensor is W^T (Dd rows), for STAGE 2 it's batched X.
    const int ay0 = z * Np + m0;
    const int by0 = (STAGE == 1) ? n0 : z * Np + n0;

    const uint32_t full0  = sb + T_OFF_MBAR;        // full[s]  = +s*8
    const uint32_t empty0 = sb + T_OFF_MBAR + 16;   // empty[s] = +16+s*8

    if (tid == 0) {
        #pragma unroll
        for (int s = 0; s < 2; s++) {
            MBARRIER_INIT(full0  + s * 8, 1);       // expect_tx arrival
            MBARRIER_INIT(empty0 + s * 8, 1);       // tcgen05.commit arrival
        }
    }
    if (wid == 0) TCGEN05_ALLOC(sb, 256);
    __syncthreads();
    uint32_t tmem;
    asm volatile("ld.shared.b32 %0, [%1];" : "=r"(tmem) : "r"(sb));
    if (wid == 0) TCGEN05_RELINQ();
    __syncthreads();

    if (wid == 0) {
        // ---- mainloop driver: whole warp stays converged; lane0 issues ----
        const uint32_t epred = elect_one_pred();
        auto issue_stage = [&](int k) {     // load k-iter k into stage k&1
            if (epred) {
                uint32_t stg = sb + T_OFF_TILES + (k & 1) * T_STAGE_BYTES;
                int kx = k * 64;            // element coord along K
                MBARRIER_EXPECT_TX(full0 + (k & 1) * 8, T_STAGE_BYTES);
                TMA_LOAD_2D(stg,                                &mAhi, kx, ay0, full0 + (k & 1) * 8);
                TMA_LOAD_2D(stg + A_TILE_BYTES,                 &mAlo, kx, ay0, full0 + (k & 1) * 8);
                TMA_LOAD_2D(stg + 2 * A_TILE_BYTES,             &mBhi, kx, by0, full0 + (k & 1) * 8);
                TMA_LOAD_2D(stg + 2 * A_TILE_BYTES + B_TILE_BYTES, &mBlo, kx, by0, full0 + (k & 1) * 8);
            }
        };

        issue_stage(0);
        issue_stage(1);

        for (int k = 0; k < T_KITERS; k++) {
            MBAR_WAIT(full0 + (k & 1) * 8, (k >> 1) & 1);
            if (epred) {
                uint32_t stg = sb + T_OFF_TILES + (k & 1) * T_STAGE_BYTES;
                uint64_t dAh = make_desc(stg);
                uint64_t dAl = make_desc(stg + A_TILE_BYTES);
                uint64_t dBh = make_desc(stg + 2 * A_TILE_BYTES);
                uint64_t dBl = make_desc(stg + 2 * A_TILE_BYTES + B_TILE_BYTES);
                #pragma unroll
                for (int s = 0; s < 4; s++) {             // four K=16 steps
                    uint64_t o = (uint64_t)(s * 2);
                    MMA_BF16_SS(tmem, dAh + o, dBh + o, T_IDESC, (k == 0 && s == 0) ? 0u : 1u);
                    MMA_BF16_SS(tmem, dAh + o, dBl + o, T_IDESC, 1u);
                    MMA_BF16_SS(tmem, dAl + o, dBh + o, T_IDESC, 1u);
                }
                TCGEN05_COMMIT(empty0 + (k & 1) * 8);
            }
            if (k + 2 < T_KITERS) {
                // stage k&1 refilled next: wait its MMAs (commit k) drained
                MBAR_WAIT(empty0 + (k & 1) * 8, (k >> 1) & 1);
                issue_stage(k + 2);
            }
        }
        // commit of k=7 is completion #4 on empty[1] -> wait parity 1
        MBAR_WAIT(empty0 + 8, 1);
    }

    __syncthreads();            // all warps see the final accumulator
    TCGEN05_FENCE_AFTER();

    // Epilogue: 8 warps. Warps 0-3 -> cols [0,128), warps 4-7 -> cols [128,256).
    {
        const int half = wid >> 2;
        const int gi   = m0 + (wid & 3) * 32 + lid;
        const int cbase = half * 128;
        if (STAGE == 1) {
            size_t base = ((size_t)z * Np + gi) * Dd + n0 + cbase;
            #pragma unroll
            for (int c0 = 0; c0 < 128; c0 += 32) {
                uint32_t r[32];
                TCGEN05_LD_X32(r, tmem + cbase + c0);
                TCGEN05_WAIT_LD();
                __align__(16) __nv_bfloat16 hs[32], ls[32];
                #pragma unroll
                for (int c = 0; c < 32; c++) {
                    float v = __uint_as_float(r[c]);
                    __nv_bfloat16 hh = __float2bfloat16_rn(v);
                    hs[c] = hh;
                    ls[c] = __float2bfloat16_rn(v - __bfloat162float(hh));
                }
                uint4* dh = reinterpret_cast<uint4*>(g_xwhi + base + c0);
                uint4* dl = reinterpret_cast<uint4*>(g_xwlo + base + c0);
                const uint4* sh = reinterpret_cast<const uint4*>(hs);
                const uint4* sl = reinterpret_cast<const uint4*>(ls);
                #pragma unroll
                for (int q = 0; q < 4; q++) { dh[q] = sh[q]; dl[q] = sl[q]; }
            }
        } else {
            const float bv = *bias;
            size_t base = ((size_t)z * Np + gi) * Np + n0 + cbase;
            #pragma unroll
            for (int c0 = 0; c0 < 128; c0 += 32) {
                uint32_t r[32];
                TCGEN05_LD_X32(r, tmem + cbase + c0);
                TCGEN05_WAIT_LD();
                __align__(16) float vs[32];
                #pragma unroll
                for (int c = 0; c < 32; c++) {
                    int gj = n0 + cbase + c0 + c;
                    float v = __uint_as_float(r[c]) + bv;
                    vs[c] = (gi == gj) ? 0.0f : v;
                }
                float4* d = reinterpret_cast<float4*>(out + base + c0);
                const float4* s = reinterpret_cast<const float4*>(vs);
                #pragma unroll
                for (int q = 0; q < 8; q++) d[q] = s[q];
            }
        }
        TCGEN05_FENCE_BEFORE();
    }
    __syncthreads();
    if (wid == 0) TCGEN05_DEALLOC(tmem, 256);
#endif  // HAS_TC
}

// ---------------------------------------------------------------------------
typedef CUresult (*cuTensorMapEncodeTiled_t)(
    CUtensorMap*, CUtensorMapDataType, cuuint32_t, void*,
    const cuuint64_t*, const cuuint64_t*, const cuuint32_t*, const cuuint32_t*,
    CUtensorMapInterleave, CUtensorMapSwizzle, CUtensorMapL2promotion,
    CUtensorMapFloatOOBfill);

extern "C" void kernel_launch(void* const* d_in, const int* in_sizes, int n_in,
                              void* d_out, int out_size) {
    const float* X    = (const float*)d_in[0];   // (32, 512, 512)
    const float* W    = (const float*)d_in[1];   // (512, 512)
    const float* bias = (const float*)d_in[2];   // scalar
    float* out = (float*)d_out;                  // (32, 512, 512)

    cudaFuncSetAttribute(gemm_tc<1>, cudaFuncAttributeMaxDynamicSharedMemorySize, T_SMEM_TOTAL);
    cudaFuncSetAttribute(gemm_tc<2>, cudaFuncAttributeMaxDynamicSharedMemorySize, T_SMEM_TOTAL);

    // Driver entry point via runtime (no -lcuda link dependency).
    cuTensorMapEncodeTiled_t enc = nullptr;
    cudaDriverEntryPointQueryResult qr;
    cudaGetDriverEntryPoint("cuTensorMapEncodeTiled", (void**)&enc,
                            cudaEnableDefault, &qr);

    void *p_xhi, *p_xlo, *p_wthi, *p_wtlo, *p_xwhi, *p_xwlo;
    cudaGetSymbolAddress(&p_xhi,  g_xhi);
    cudaGetSymbolAddress(&p_xlo,  g_xlo);
    cudaGetSymbolAddress(&p_wthi, g_wthi);
    cudaGetSymbolAddress(&p_wtlo, g_wtlo);
    cudaGetSymbolAddress(&p_xwhi, g_xwhi);
    cudaGetSymbolAddress(&p_xwlo, g_xwlo);

    auto make2d = [&](void* base, uint64_t rows, uint32_t boxRows) {
        CUtensorMap m{};
        cuuint64_t dims[2]    = {(cuuint64_t)Dd, rows};   // inner = 512 bf16
        cuuint64_t strides[1] = {(cuuint64_t)Dd * 2};     // 1024 B row pitch
        cuuint32_t box[2]     = {64, boxRows};            // 64 bf16 = 128B = SW128
        cuuint32_t es[2]      = {1, 1};
        enc(&m, CU_TENSOR_MAP_DATA_TYPE_BFLOAT16, 2, base, dims, strides, box, es,
            CU_TENSOR_MAP_INTERLEAVE_NONE, CU_TENSOR_MAP_SWIZZLE_128B,
            CU_TENSOR_MAP_L2_PROMOTION_L2_128B, CU_TENSOR_MAP_FLOAT_OOB_FILL_NONE);
        return m;
    };

    const uint64_t XROWS = (uint64_t)Bb * Np;
    CUtensorMap m_xhiA  = make2d(p_xhi,  XROWS, 128);
    CUtensorMap m_xloA  = make2d(p_xlo,  XROWS, 128);
    CUtensorMap m_wthiB = make2d(p_wthi, Dd,    256);
    CUtensorMap m_wtloB = make2d(p_wtlo, Dd,    256);
    CUtensorMap m_xwhiA = make2d(p_xwhi, XROWS, 128);
    CUtensorMap m_xwloA = make2d(p_xwlo, XROWS, 128);
    CUtensorMap m_xhiB  = make2d(p_xhi,  XROWS, 256);
    CUtensorMap m_xloB  = make2d(p_xlo,  XROWS, 256);

    conv_w_kernel<<<dim3(16, 16), dim3(32, 8)>>>(W);
    conv_x_kernel<<<(Bb * Np * Dd) / 4 / 256, 256>>>((const float4*)X);

    dim3 grid(Np / TBN, Np / TBM, Bb);   // (2, 4, 32) = 256 CTAs
    gemm_tc<1><<<grid, 256, T_SMEM_TOTAL>>>(bias, out, m_xhiA, m_xloA, m_wthiB, m_wtloB);
    gemm_tc<2><<<grid, 256, T_SMEM_TOTAL>>>(bias, out, m_xwhiA, m_xwloA, m_xhiB, m_xloB);
}